// round 15
// baseline (speedup 1.0000x reference)
#include <cuda_runtime.h>
#include <cuda_fp16.h>
#include <math.h>
#include <stdint.h>

// ---------------------------------------------------------------------------
// TensorProductMultiLayerPerceptron — Round 15: R14 + float2 weight loads,
// hoisted before MMA (L1-wavefront cut on the weighted-accumulate path).
//
// Per (p, u, wh, kz) CTA, loop quads of 2 v (16 iters over 32 v):
//   Bb^T[w, b] = P_p[x,u,v,w]^T @ hs[b,x]^T      (fp16 mma, fp32 acc)
//   p0/p2: Tacc       += s2[v,b]   * Bb^T        (1 set)
//   p1/p3/p4: Tacc[j] += v2[j,v,b] * Bb^T        (3 sets, uniform)
// Epilogue (linearity):
//   p0: s1*T   p1: s1*T_j   p2: v1_i*T   p3: dot(v1,T)   p4: cross(v1,T)_k
// atomicAdd into g_T[1408 x 64]; combine assembles output.
// ---------------------------------------------------------------------------

#define NROWS 1408

__device__ __half g_hsh[128 * 64];
__device__ float  g_s2t[64 * 128];          // [v][b] = s2[b,v]
__device__ float  g_v2t[3 * 64 * 128];      // [j][v][b] = v2[b,v,j]
__device__ float  g_T[NROWS * 64];

// ---------------- helpers ----------------
__device__ __forceinline__ uint32_t smem_u32(const void* p) {
    uint32_t a;
    asm("{ .reg .u64 t; cvta.to.shared.u64 t, %1; cvt.u32.u64 %0, t; }"
        : "=r"(a) : "l"(p));
    return a;
}
__device__ __forceinline__ void cp16(uint32_t s, const void* g) {
    asm volatile("cp.async.cg.shared.global [%0], [%1], 16;\n" :: "r"(s), "l"(g));
}
#define CP_COMMIT() asm volatile("cp.async.commit_group;\n" ::: "memory")
#define CP_WAIT(n)  asm volatile("cp.async.wait_group %0;\n" :: "n"(n) : "memory")

#define LDSM4(r, addr) \
    asm volatile("ldmatrix.sync.aligned.m8n8.x4.shared.b16 {%0,%1,%2,%3}, [%4];" \
        : "=r"((r)[0]), "=r"((r)[1]), "=r"((r)[2]), "=r"((r)[3]) : "r"(addr))
#define LDSM4T(r, addr) \
    asm volatile("ldmatrix.sync.aligned.m8n8.x4.trans.shared.b16 {%0,%1,%2,%3}, [%4];" \
        : "=r"((r)[0]), "=r"((r)[1]), "=r"((r)[2]), "=r"((r)[3]) : "r"(addr))
#define MMA16816(d, a0, a1, a2, a3, b0, b1) \
    asm volatile("mma.sync.aligned.m16n8k16.row.col.f32.f16.f16.f32 " \
        "{%0,%1,%2,%3},{%4,%5,%6,%7},{%8,%9},{%0,%1,%2,%3};" \
        : "+f"((d)[0]), "+f"((d)[1]), "+f"((d)[2]), "+f"((d)[3]) \
        : "r"(a0), "r"(a1), "r"(a2), "r"(a3), "r"(b0), "r"(b1))

__device__ __forceinline__ uint32_t pack_h2(float a, float b) {
    __half2 h = __floats2half2_rn(a, b);
    return *reinterpret_cast<uint32_t*>(&h);
}
__device__ __forceinline__ float gelu_tanh(float x) {
    float x3 = x * x * x;
    return 0.5f * x * (1.0f + tanhf(0.7978845608028654f * (x + 0.044715f * x3)));
}

// ---------------------------------------------------------------------------
// Kernel 1: MLP  emb(128x64) -> hs fp16
// ---------------------------------------------------------------------------
__global__ __launch_bounds__(256) void mlp_kernel(
    const float* __restrict__ emb, const float* __restrict__ W0,
    const float* __restrict__ W1, const float* __restrict__ W2, float phi_inv)
{
    __shared__ float sa[256];
    __shared__ float sb[256];
    int b = blockIdx.x;
    int t = threadIdx.x;

    if (t < 64) sa[t] = emb[b * 64 + t];
    __syncthreads();

    float acc = 0.0f;
#pragma unroll 8
    for (int k = 0; k < 64; k++) acc += sa[k] * W0[k * 256 + t];
    sb[t] = gelu_tanh(acc * 0.125f) * phi_inv;
    __syncthreads();

    acc = 0.0f;
#pragma unroll 8
    for (int k = 0; k < 256; k++) acc += sb[k] * W1[k * 256 + t];
    float v2l = gelu_tanh(acc * 0.0625f) * phi_inv;
    __syncthreads();
    sa[t] = v2l;
    __syncthreads();

    if (t < 64) {
        acc = 0.0f;
#pragma unroll 8
        for (int k = 0; k < 256; k++) acc += sa[k] * W2[k * 64 + t];
        g_hsh[b * 64 + t] = __float2half(gelu_tanh(acc * 0.0625f) * phi_inv * 0.125f);
    }
}

// ---------------------------------------------------------------------------
// Kernel 2: s2t/v2t tables + zero g_T
// ---------------------------------------------------------------------------
__global__ __launch_bounds__(1024) void prep_kernel(const float* __restrict__ x2)
{
    int idx = blockIdx.x * 1024 + threadIdx.x;
    if (idx < NROWS * 64) g_T[idx] = 0.0f;
    if (blockIdx.x < 8) {
        int v = blockIdx.x * 8 + (threadIdx.x >> 7);
        int b = threadIdx.x & 127;
        g_s2t[v * 128 + b] = x2[b * 256 + v];
#pragma unroll
        for (int j = 0; j < 3; j++)
            g_v2t[j * 8192 + v * 128 + b] = x2[b * 256 + 64 + v * 3 + j];
    }
}

// ---------------------------------------------------------------------------
// Kernel 3: fused GEMM (transposed).  grid (64 u, 2 wh, 10 = p*2+kz), 256 thr.
// smem: hs 16K | praw 3 x 16K | wtab 4 x 3K | bh 2 x 8K | u-slices 2K.
// ---------------------------------------------------------------------------
#define SM_HS 0
#define SM_PR 16384
#define SM_WT 65536
#define SM_BH 77824
#define SM_U  94208
#define FUSED_DSMEM 96256
#define NQUAD 16

extern __shared__ char dsm[];

__global__ void __launch_bounds__(256, 2) fused_kernel(
    const float* __restrict__ p0, const float* __restrict__ p1,
    const float* __restrict__ p2, const float* __restrict__ p3,
    const float* __restrict__ p4, const float* __restrict__ x1)
{
    uint32_t sb = smem_u32(dsm);

    int t = threadIdx.x;
    int lane = t & 31;
    int warp = t >> 5;
    int wm = warp >> 2;          // 0..1  (w m16-tile)
    int bn = warp & 3;           // 0..3  (b n32-tile)
    int u  = blockIdx.x;
    int wh = blockIdx.y;
    int p  = blockIdx.z >> 1;
    int kz = blockIdx.z & 1;
    int v0 = kz * 32;

    const float* P = (p == 0) ? p0 : (p == 1) ? p1 : (p == 2) ? p2
                   : (p == 3) ? p3 : p4;

    // weight-table source: s2 (1 set) for p0/p2; v2 (3 sets) for p1/p3/p4
    const float* wsrc;
    int nsets;
    if (p == 0 || p == 2) { wsrc = g_s2t; nsets = 1; }
    else                  { wsrc = g_v2t; nsets = 3; }

    // ---- stage hs (128 x 64 fp16, swizzled) ----
#pragma unroll
    for (int j = 0; j < 4; j++) {
        int idx = t + j * 256;
        int m = idx >> 3, c = idx & 7;
        cp16(sb + SM_HS + m * 128 + ((c ^ (m & 7)) << 4), g_hsh + m * 64 + c * 8);
    }

    // ---- stage u-slices (plain stores, sealed by first barrier) ----
    {
        float* s1u = (float*)(dsm + SM_U);
        if (t < 128) {
            s1u[t]       = x1[t * 256 + u];
            s1u[128 + t] = x1[t * 256 + 64 + u * 3 + 0];
            s1u[256 + t] = x1[t * 256 + 64 + u * 3 + 1];
            s1u[384 + t] = x1[t * 256 + 64 + u * 3 + 2];
        }
    }

    // P loader coords: per quad (2 v), thread loads 4 chunks of 16B.
    const float* pbase = P + (size_t)((t >> 3) * 64 + u) * 4096
                       + (size_t)v0 * 64 + wh * 32 + (t & 7) * 4;
    uint32_t pdst = (uint32_t)(SM_PR + (t >> 3) * 128 + (t & 7) * 16);
    const size_t XSTEP = (size_t)32 * 64 * 4096;

    auto issue_quad = [&](int q) {
        const float* src = pbase + (size_t)q * 128;
        uint32_t d = sb + pdst + (uint32_t)(q % 3) * 16384;
#pragma unroll
        for (int j = 0; j < 4; j++)
            cp16(d + (j >> 1) * 8192 + (j & 1) * 4096,
                 src + (j & 1) * XSTEP + (size_t)(j >> 1) * 64);
        int v = v0 + q * 2;
        uint32_t wd = sb + SM_WT + (uint32_t)(q & 3) * 3072;
        if (t < nsets * 64) {
            int s = t >> 6, idx = t & 63;
            int vv = idx >> 5, cc = idx & 31;
            cp16(wd + s * 1024 + vv * 512 + cc * 16,
                 wsrc + (size_t)s * 8192 + (size_t)(v + vv) * 128 + cc * 4);
        }
    };

    issue_quad(0); CP_COMMIT();
    issue_quad(1); CP_COMMIT();
    issue_quad(2); CP_COMMIT();

    CP_WAIT(2);                  // hs + q0 arrived
    __syncthreads();

    int krl = lane & 15;
    int hi  = lane >> 4;
    int tg  = lane & 3;          // float2 index within 8-b group
    int tg2 = tg * 2;

    // ---- persistent hs B-fragments: n32 (b) x k64, 32 regs ----
    uint32_t bfr[4][8];
    {
#pragma unroll
        for (int kk = 0; kk < 4; kk++) {
            int c = kk * 2 + hi;
            uint32_t q1[4], q2[4];
            int row = bn * 32 + krl;
            LDSM4(q1, sb + SM_HS + row * 128 + ((c ^ (row & 7)) << 4));
            row += 16;
            LDSM4(q2, sb + SM_HS + row * 128 + ((c ^ (row & 7)) << 4));
            bfr[kk][0] = q1[0]; bfr[kk][1] = q1[2];   // n-tile 0 (b +0..7)
            bfr[kk][2] = q1[1]; bfr[kk][3] = q1[3];   // n-tile 1 (b +8..15)
            bfr[kk][4] = q2[0]; bfr[kk][5] = q2[2];   // n-tile 2
            bfr[kk][6] = q2[1]; bfr[kk][7] = q2[3];   // n-tile 3
        }
    }

    float Tacc[48];
#pragma unroll
    for (int i = 0; i < 48; i++) Tacc[i] = 0.0f;

    // convert coords (praw[x][w] fp32 -> bh[x][w] fp16, swizzled)
    int kq = t >> 2, cq = t & 3;
    uint32_t cvt_src = (uint32_t)(SM_PR + kq * 128 + cq * 32);
    uint32_t cvt_dst = (uint32_t)(SM_BH + kq * 64 + ((cq ^ ((kq >> 1) & 3)) << 4));

    auto convert_quad = [&](int q) {
        const char* srcb = dsm + cvt_src + (q % 3) * 16384;
        char* dstb = dsm + cvt_dst + (q & 1) * 8192;
#pragma unroll
        for (int vv = 0; vv < 2; vv++) {
            const float4* src = (const float4*)(srcb + vv * 8192);
            float4 f0 = src[0], f1 = src[1];
            *(uint4*)(dstb + vv * 4096) =
                make_uint4(pack_h2(f0.x, f0.y), pack_h2(f0.z, f0.w),
                           pack_h2(f1.x, f1.y), pack_h2(f1.z, f1.w));
        }
    };

    convert_quad(0);
    CP_WAIT(1);
    __syncthreads();

    // float2 weight index base: (vv*128 + s*256 + b0) / 2 with
    // b0 = bn*32 + nj*8 + tg2  ->  half-index = bn*16 + nj*4 + tg
    int wtb = bn * 16 + tg;

    // ================= main loop: 16 quads of 2 v =================
#pragma unroll 1
    for (int i = 0; i < NQUAD; i++) {
        if (i + 3 < NQUAD) { issue_quad(i + 3); CP_COMMIT(); CP_WAIT(1); }
        else CP_WAIT(0);

        const float2* wt2 = (const float2*)(dsm + SM_WT + (i & 3) * 3072);

#pragma unroll
        for (int vv = 0; vv < 2; vv++) {
            // ---- hoisted weight loads (float2; latency overlaps MMA) ----
            float2 wreg[3][4];
            if (nsets == 1) {
#pragma unroll
                for (int nj = 0; nj < 4; nj++)
                    wreg[0][nj] = wt2[vv * 64 + wtb + nj * 4];
            } else {
#pragma unroll
                for (int s = 0; s < 3; s++)
#pragma unroll
                    for (int nj = 0; nj < 4; nj++)
                        wreg[s][nj] = wt2[vv * 64 + s * 128 + wtb + nj * 4];
            }

            float acc[4][4];
#pragma unroll
            for (int nj = 0; nj < 4; nj++)
#pragma unroll
                for (int q = 0; q < 4; q++) acc[nj][q] = 0.0f;

            uint32_t bhbase = sb + SM_BH + (i & 1) * 8192 + vv * 4096;
#pragma unroll
            for (int kk = 0; kk < 4; kk++) {
                int krow = kk * 16 + krl;
                uint32_t c = (uint32_t)(wm * 2 + hi);
                uint32_t r[4];
                LDSM4T(r, bhbase + krow * 64 + ((c ^ ((uint32_t)(krow >> 1) & 3)) << 4));
                // A-frags {a0,a1,a2,a3} = {r0, r2, r1, r3}
                MMA16816(acc[0], r[0], r[2], r[1], r[3], bfr[kk][0], bfr[kk][1]);
                MMA16816(acc[1], r[0], r[2], r[1], r[3], bfr[kk][2], bfr[kk][3]);
                MMA16816(acc[2], r[0], r[2], r[1], r[3], bfr[kk][4], bfr[kk][5]);
                MMA16816(acc[3], r[0], r[2], r[1], r[3], bfr[kk][6], bfr[kk][7]);
            }

            if (nsets == 1) {
#pragma unroll
                for (int nj = 0; nj < 4; nj++) {
                    float w0 = wreg[0][nj].x, w1 = wreg[0][nj].y;
                    Tacc[nj * 4 + 0] += w0 * acc[nj][0];
                    Tacc[nj * 4 + 1] += w1 * acc[nj][1];
                    Tacc[nj * 4 + 2] += w0 * acc[nj][2];
                    Tacc[nj * 4 + 3] += w1 * acc[nj][3];
                }
            } else {
#pragma unroll
                for (int s = 0; s < 3; s++)
#pragma unroll
                    for (int nj = 0; nj < 4; nj++) {
                        float w0 = wreg[s][nj].x, w1 = wreg[s][nj].y;
                        Tacc[s * 16 + nj * 4 + 0] += w0 * acc[nj][0];
                        Tacc[s * 16 + nj * 4 + 1] += w1 * acc[nj][1];
                        Tacc[s * 16 + nj * 4 + 2] += w0 * acc[nj][2];
                        Tacc[s * 16 + nj * 4 + 3] += w1 * acc[nj][3];
                    }
            }
        }

        if (i + 1 < NQUAD) convert_quad(i + 1);
        __syncthreads();
    }

    // ---- epilogue: u-factor + atomicAdd ----
    const float* s1u = (const float*)(dsm + SM_U);          // [128]
    const float* v1u = s1u + 128;                            // [3][128]
    int wc = wh * 32 + wm * 16 + (lane >> 2);

    if (p == 0) {
#pragma unroll
        for (int nj = 0; nj < 4; nj++) {
            int b0 = bn * 32 + nj * 8 + tg2, b1 = b0 + 1;
            float f0 = s1u[b0], f1 = s1u[b1];
            atomicAdd(&g_T[b0 * 64 + wc],     f0 * Tacc[nj * 4 + 0]);
            atomicAdd(&g_T[b1 * 64 + wc],     f1 * Tacc[nj * 4 + 1]);
            atomicAdd(&g_T[b0 * 64 + wc + 8], f0 * Tacc[nj * 4 + 2]);
            atomicAdd(&g_T[b1 * 64 + wc + 8], f1 * Tacc[nj * 4 + 3]);
        }
    } else if (p == 1) {
#pragma unroll
        for (int s = 0; s < 3; s++)
#pragma unroll
            for (int nj = 0; nj < 4; nj++) {
                int b0 = bn * 32 + nj * 8 + tg2, b1 = b0 + 1;
                float f0 = s1u[b0], f1 = s1u[b1];
                int r0 = 128 + 3 * b0 + s, r1 = 128 + 3 * b1 + s;
                atomicAdd(&g_T[r0 * 64 + wc],     f0 * Tacc[s * 16 + nj * 4 + 0]);
                atomicAdd(&g_T[r1 * 64 + wc],     f1 * Tacc[s * 16 + nj * 4 + 1]);
                atomicAdd(&g_T[r0 * 64 + wc + 8], f0 * Tacc[s * 16 + nj * 4 + 2]);
                atomicAdd(&g_T[r1 * 64 + wc + 8], f1 * Tacc[s * 16 + nj * 4 + 3]);
            }
    } else if (p == 2) {
#pragma unroll
        for (int s = 0; s < 3; s++)
#pragma unroll
            for (int nj = 0; nj < 4; nj++) {
                int b0 = bn * 32 + nj * 8 + tg2, b1 = b0 + 1;
                float f0 = v1u[s * 128 + b0], f1 = v1u[s * 128 + b1];
                int r0 = 512 + 3 * b0 + s, r1 = 512 + 3 * b1 + s;
                atomicAdd(&g_T[r0 * 64 + wc],     f0 * Tacc[nj * 4 + 0]);
                atomicAdd(&g_T[r1 * 64 + wc],     f1 * Tacc[nj * 4 + 1]);
                atomicAdd(&g_T[r0 * 64 + wc + 8], f0 * Tacc[nj * 4 + 2]);
                atomicAdd(&g_T[r1 * 64 + wc + 8], f1 * Tacc[nj * 4 + 3]);
            }
    } else if (p == 3) {
        // T row 896+b: dot(v1, Tacc-sets)
#pragma unroll
        for (int nj = 0; nj < 4; nj++) {
            int b0 = bn * 32 + nj * 8 + tg2, b1 = b0 + 1;
            float a0 = v1u[b0], a1 = v1u[128 + b0], a2 = v1u[256 + b0];
            float c0 = v1u[b1], c1 = v1u[128 + b1], c2 = v1u[256 + b1];
            float s00 = a0 * Tacc[nj*4+0] + a1 * Tacc[16+nj*4+0] + a2 * Tacc[32+nj*4+0];
            float s01 = c0 * Tacc[nj*4+1] + c1 * Tacc[16+nj*4+1] + c2 * Tacc[32+nj*4+1];
            float s02 = a0 * Tacc[nj*4+2] + a1 * Tacc[16+nj*4+2] + a2 * Tacc[32+nj*4+2];
            float s03 = c0 * Tacc[nj*4+3] + c1 * Tacc[16+nj*4+3] + c2 * Tacc[32+nj*4+3];
            atomicAdd(&g_T[(896 + b0) * 64 + wc],     s00);
            atomicAdd(&g_T[(896 + b1) * 64 + wc],     s01);
            atomicAdd(&g_T[(896 + b0) * 64 + wc + 8], s02);
            atomicAdd(&g_T[(896 + b1) * 64 + wc + 8], s03);
        }
    } else {
        // T rows 1024+3b+k: cross(v1, Tacc-sets)_k
#pragma unroll
        for (int nj = 0; nj < 4; nj++) {
            int b0 = bn * 32 + nj * 8 + tg2, b1 = b0 + 1;
            float va[3] = { v1u[b0], v1u[128 + b0], v1u[256 + b0] };
            float vb[3] = { v1u[b1], v1u[128 + b1], v1u[256 + b1] };
#pragma unroll
            for (int k = 0; k < 3; k++) {
                int k1 = (k + 1) % 3, k2 = (k + 2) % 3;
                float o0 = va[k1] * Tacc[k2*16 + nj*4 + 0] - va[k2] * Tacc[k1*16 + nj*4 + 0];
                float o1 = vb[k1] * Tacc[k2*16 + nj*4 + 1] - vb[k2] * Tacc[k1*16 + nj*4 + 1];
                float o2 = va[k1] * Tacc[k2*16 + nj*4 + 2] - va[k2] * Tacc[k1*16 + nj*4 + 2];
                float o3 = vb[k1] * Tacc[k2*16 + nj*4 + 3] - vb[k2] * Tacc[k1*16 + nj*4 + 3];
                atomicAdd(&g_T[(1024 + 3 * b0 + k) * 64 + wc],     o0);
                atomicAdd(&g_T[(1024 + 3 * b1 + k) * 64 + wc],     o1);
                atomicAdd(&g_T[(1024 + 3 * b0 + k) * 64 + wc + 8], o2);
                atomicAdd(&g_T[(1024 + 3 * b1 + k) * 64 + wc + 8], o3);
            }
        }
    }
}

// ---------------------------------------------------------------------------
// Kernel 4: combine — assemble output from g_T
// ---------------------------------------------------------------------------
__global__ __launch_bounds__(448) void combine_kernel(float* __restrict__ out)
{
    int b = blockIdx.x;
    int t = threadIdx.x;
    const float C = 0.011048543456039806f;       // 1/(64*sqrt(2))
    const float INV_SQ3 = 0.5773502691896258f;

    if (t < 64) {
        int w = t;
        out[b * 448 + w] = C * (g_T[b * 64 + w] + INV_SQ3 * g_T[(896 + b) * 64 + w]);
    } else if (t < 256) {
        int i = t - 64;
        int w = i / 3, c = i % 3;
        out[b * 448 + 64 + w * 3 + c] =
            C * (g_T[(128 + b * 3 + c) * 64 + w] + g_T[(512 + b * 3 + c) * 64 + w]);
    } else {
        int i = t - 256;
        int w = i / 3, k = i % 3;
        out[b * 448 + 256 + w * 3 + k] = C * g_T[(1024 + b * 3 + k) * 64 + w];
    }
}

// ---------------------------------------------------------------------------
static double host_phi_c()
{
    const double dz = 16.0 / 4000.0;
    const double inv_sqrt2pi = 0.3989422804014327;
    double sum = 0.0, prev = 0.0;
    for (int i = 0; i <= 4000; i++) {
        double z = -8.0 + dz * (double)i;
        float xf = (float)z;
        float x3 = xf * xf * xf;
        float gg = 0.5f * xf * (1.0f + tanhf(0.7978845608028654f * (xf + 0.044715f * x3)));
        double f = (double)gg * (double)gg * exp(-0.5 * z * z) * inv_sqrt2pi;
        if (i > 0) sum += 0.5 * (f + prev) * dz;
        prev = f;
    }
    return sqrt(sum);
}

extern "C" void kernel_launch(void* const* d_in, const int* in_sizes, int n_in,
                              void* d_out, int out_size)
{
    const float* emb = (const float*)d_in[0];
    const float* x1  = (const float*)d_in[1];
    const float* x2  = (const float*)d_in[2];
    const float* W0  = (const float*)d_in[3];
    const float* W1  = (const float*)d_in[4];
    const float* W2  = (const float*)d_in[5];
    const float* P0  = (const float*)d_in[6];
    const float* P1  = (const float*)d_in[7];
    const float* P2  = (const float*)d_in[8];
    const float* P3  = (const float*)d_in[9];
    const float* P4  = (const float*)d_in[10];
    float* out = (float*)d_out;

    float phi_inv = (float)(1.0 / host_phi_c());

    cudaFuncSetAttribute(fused_kernel,
                         cudaFuncAttributeMaxDynamicSharedMemorySize, FUSED_DSMEM);

    mlp_kernel<<<128, 256>>>(emb, W0, W1, W2, phi_inv);
    prep_kernel<<<88, 1024>>>(x2);
    fused_kernel<<<dim3(64, 2, 10), 256, FUSED_DSMEM>>>(P0, P1, P2, P3, P4, x1);
    combine_kernel<<<128, 448>>>(out);
}

// round 16
// speedup vs baseline: 1.2226x; 1.2226x over previous
#include <cuda_runtime.h>
#include <cuda_fp16.h>
#include <math.h>
#include <stdint.h>

// ---------------------------------------------------------------------------
// TensorProductMultiLayerPerceptron — Round 16: revert to R10 (best, 154.0us)
// + heavy-first CTA ordering + p4 cross moved to epilogue (linearity).
//
// For each (p, u, wh, kz) CTA, loop quads of 2 v (16 iterations over 32 v):
//   Bb[b, w] = sum_x hs[b,x] * P_p[x, u, v, w]        (fp16 mma, fp32 acc)
//   T_acc[set][b, w] += weight_p(b, v) * Bb[b, w]     (registers, w from smem)
//     p0/p2: 1 set (s2);  p3: 1 set (dot, in-loop);  p1/p4: 3 sets (v2)
// Epilogue: u-factor (p4: cross(v1, Tsets)), atomicAdd into g_T[1408 x 64].
// ---------------------------------------------------------------------------

#define NROWS 1408

__device__ __half g_hsh[128 * 64];
__device__ float  g_s2t[64 * 128];        // [v][b] = s2[b,v]
__device__ float  g_v2t[3][64 * 128];     // [j][v][b] = v2[b,v,j]
__device__ float  g_T[NROWS * 64];

// ---------------- helpers ----------------
__device__ __forceinline__ uint32_t smem_u32(const void* p) {
    uint32_t a;
    asm("{ .reg .u64 t; cvta.to.shared.u64 t, %1; cvt.u32.u64 %0, t; }"
        : "=r"(a) : "l"(p));
    return a;
}
__device__ __forceinline__ void cp16(uint32_t s, const void* g) {
    asm volatile("cp.async.cg.shared.global [%0], [%1], 16;\n" :: "r"(s), "l"(g));
}
#define CP_COMMIT() asm volatile("cp.async.commit_group;\n" ::: "memory")
#define CP_WAIT(n)  asm volatile("cp.async.wait_group %0;\n" :: "n"(n) : "memory")

#define LDSM4(r, addr) \
    asm volatile("ldmatrix.sync.aligned.m8n8.x4.shared.b16 {%0,%1,%2,%3}, [%4];" \
        : "=r"((r)[0]), "=r"((r)[1]), "=r"((r)[2]), "=r"((r)[3]) : "r"(addr))
#define LDSM4T(r, addr) \
    asm volatile("ldmatrix.sync.aligned.m8n8.x4.trans.shared.b16 {%0,%1,%2,%3}, [%4];" \
        : "=r"((r)[0]), "=r"((r)[1]), "=r"((r)[2]), "=r"((r)[3]) : "r"(addr))
#define MMA16816(d, a, b0, b1) \
    asm volatile("mma.sync.aligned.m16n8k16.row.col.f32.f16.f16.f32 " \
        "{%0,%1,%2,%3},{%4,%5,%6,%7},{%8,%9},{%0,%1,%2,%3};" \
        : "+f"((d)[0]), "+f"((d)[1]), "+f"((d)[2]), "+f"((d)[3]) \
        : "r"((a)[0]), "r"((a)[1]), "r"((a)[2]), "r"((a)[3]), "r"(b0), "r"(b1))

__device__ __forceinline__ uint32_t pack_h2(float a, float b) {
    __half2 h = __floats2half2_rn(a, b);
    return *reinterpret_cast<uint32_t*>(&h);
}
__device__ __forceinline__ float gelu_tanh(float x) {
    float x3 = x * x * x;
    return 0.5f * x * (1.0f + tanhf(0.7978845608028654f * (x + 0.044715f * x3)));
}

// ---------------------------------------------------------------------------
// Kernel 1: MLP  emb(128x64) -> hs fp16
// ---------------------------------------------------------------------------
__global__ __launch_bounds__(256) void mlp_kernel(
    const float* __restrict__ emb, const float* __restrict__ W0,
    const float* __restrict__ W1, const float* __restrict__ W2, float phi_inv)
{
    __shared__ float sa[256];
    __shared__ float sb[256];
    int b = blockIdx.x;
    int t = threadIdx.x;

    if (t < 64) sa[t] = emb[b * 64 + t];
    __syncthreads();

    float acc = 0.0f;
#pragma unroll 8
    for (int k = 0; k < 64; k++) acc += sa[k] * W0[k * 256 + t];
    sb[t] = gelu_tanh(acc * 0.125f) * phi_inv;
    __syncthreads();

    acc = 0.0f;
#pragma unroll 8
    for (int k = 0; k < 256; k++) acc += sb[k] * W1[k * 256 + t];
    float v2l = gelu_tanh(acc * 0.0625f) * phi_inv;
    __syncthreads();
    sa[t] = v2l;
    __syncthreads();

    if (t < 64) {
        acc = 0.0f;
#pragma unroll 8
        for (int k = 0; k < 256; k++) acc += sa[k] * W2[k * 64 + t];
        g_hsh[b * 64 + t] = __float2half(gelu_tanh(acc * 0.0625f) * phi_inv * 0.125f);
    }
}

// ---------------------------------------------------------------------------
// Kernel 2: weight tables + zero g_T  (grid 88, block 1024)
// ---------------------------------------------------------------------------
__global__ __launch_bounds__(1024) void prep_kernel(const float* __restrict__ x2)
{
    int idx = blockIdx.x * 1024 + threadIdx.x;
    if (idx < NROWS * 64) g_T[idx] = 0.0f;
    if (blockIdx.x < 8) {
        int v = blockIdx.x * 8 + (threadIdx.x >> 7);
        int b = threadIdx.x & 127;
        g_s2t[v * 128 + b] = x2[b * 256 + v];
#pragma unroll
        for (int j = 0; j < 3; j++)
            g_v2t[j][v * 128 + b] = x2[b * 256 + 64 + v * 3 + j];
    }
}

// ---------------------------------------------------------------------------
// Kernel 3: fused GEMM.  grid (64 u, 2 wh, 10 = zp*2+kz), 256 threads.
// zp -> p via heavy-first map {1,4,3,0,2} (3-set CTAs launch first, the
// 1-set CTAs back-fill the scheduling tail).
// smem: hs 16K | praw 3 x 16K (2-v quads fp32) | wtab 4 x 3K | bh 2 x 8K.
// Pipeline (1 barrier/iter): issue q(i+3); wait; MMA quad i; convert q(i+1).
// wtab 4-deep (quad i reads wtab[i&3], quad i+3 writes wtab[(i+3)&3]).
// ---------------------------------------------------------------------------
#define SM_HS 0
#define SM_PR 16384
#define SM_WT 65536
#define SM_BH 77824
#define FUSED_DSMEM 94208
#define NQUAD 16

extern __shared__ char dsm[];

__global__ void __launch_bounds__(256, 2) fused_kernel(
    const float* __restrict__ p0, const float* __restrict__ p1,
    const float* __restrict__ p2, const float* __restrict__ p3,
    const float* __restrict__ p4, const float* __restrict__ x1)
{
    uint32_t sb = smem_u32(dsm);

    int t = threadIdx.x;
    int lane = t & 31;
    int wid = t >> 5;            // 0..7 -> m16 tile
    int u  = blockIdx.x;         // 0..63
    int wh = blockIdx.y;         // 0..1
    int zp = blockIdx.z >> 1;    // 0..4
    int kz = blockIdx.z & 1;     // 0..1
    int v0 = kz * 32;

    // heavy-first ordering: 3-set CTAs (p1, p4) first, light (p0, p2) last
    const int PMAP[5] = {1, 4, 3, 0, 2};
    int p = PMAP[zp];

    const float* P = (p == 0) ? p0 : (p == 1) ? p1 : (p == 2) ? p2
                   : (p == 3) ? p3 : p4;
    bool lightW = (p == 0 || p == 2);

    // ---- stage hs (128 x 64 fp16, swizzled) ----
#pragma unroll
    for (int j = 0; j < 4; j++) {
        int idx = t + j * 256;
        int m = idx >> 3, c = idx & 7;
        cp16(sb + SM_HS + m * 128 + ((c ^ (m & 7)) << 4), g_hsh + m * 64 + c * 8);
    }

    // P loader coords: per quad (2 v), thread loads 4 chunks of 16B.
    const float* pbase = P + (size_t)((t >> 3) * 64 + u) * 4096
                       + (size_t)v0 * 64 + wh * 32 + (t & 7) * 4;
    uint32_t pdst = (uint32_t)(SM_PR + (t >> 3) * 128 + (t & 7) * 16);
    const size_t XSTEP = (size_t)32 * 64 * 4096;   // x += 32

    // issue quad q (praw buf q%3, wtab buf q&3), no commit
    auto issue_quad = [&](int q) {
        const float* src = pbase + (size_t)q * 128;
        uint32_t d = sb + pdst + (uint32_t)(q % 3) * 16384;
#pragma unroll
        for (int j = 0; j < 4; j++)
            cp16(d + (j >> 1) * 8192 + (j & 1) * 4096,
                 src + (j & 1) * XSTEP + (size_t)(j >> 1) * 64);
        int v = v0 + q * 2;
        uint32_t wd = sb + SM_WT + (uint32_t)(q & 3) * 3072;
        if (lightW) {
            if (t < 64)
                cp16(wd + (t >> 5) * 1536 + (t & 31) * 16,
                     g_s2t + (size_t)(v + (t >> 5)) * 128 + (t & 31) * 4);
        } else {
            if (t < 192) {
                int vv = t / 96, rem = t - vv * 96, j = rem >> 5, cc = rem & 31;
                cp16(wd + vv * 1536 + j * 512 + cc * 16,
                     g_v2t[j] + (size_t)(v + vv) * 128 + cc * 4);
            }
        }
    };

    // prologue: groups = {hs+q0}, {q1}, {q2}
    issue_quad(0); CP_COMMIT();
    issue_quad(1); CP_COMMIT();
    issue_quad(2); CP_COMMIT();

    CP_WAIT(2);                  // hs + q0 arrived
    __syncthreads();

    // persistent hs A-fragments
    uint32_t af[4][4];
    {
        int row = wid * 16 + (lane & 15);
        int h2 = lane >> 4;
#pragma unroll
        for (int kk = 0; kk < 4; kk++) {
            int c = kk * 2 + h2;
            LDSM4(af[kk], sb + SM_HS + row * 128 + ((c ^ (row & 7)) << 4));
        }
    }

    int b1 = wid * 16 + (lane >> 2);
    int b2 = b1 + 8;
    float v1a[3], v1b[3];
#pragma unroll
    for (int i = 0; i < 3; i++) {
        v1a[i] = x1[b1 * 256 + 64 + u * 3 + i];
        v1b[i] = x1[b2 * 256 + 64 + u * 3 + i];
    }

    float Tacc[48];
#pragma unroll
    for (int i = 0; i < 48; i++) Tacc[i] = 0.0f;

    int hi = lane >> 4;
    int krl = lane & 15;

    // convert coords
    int kq = t >> 2, cq = t & 3;
    uint32_t cvt_src = (uint32_t)(SM_PR + kq * 128 + cq * 32);
    uint32_t cvt_dst = (uint32_t)(SM_BH + kq * 64 + ((cq ^ ((kq >> 1) & 3)) << 4));

    auto convert_quad = [&](int q) {   // praw[q%3] -> bh[q&1]
        const char* srcb = dsm + cvt_src + (q % 3) * 16384;
        char* dstb = dsm + cvt_dst + (q & 1) * 8192;
#pragma unroll
        for (int vv = 0; vv < 2; vv++) {
            const float4* src = (const float4*)(srcb + vv * 8192);
            float4 f0 = src[0], f1 = src[1];
            *(uint4*)(dstb + vv * 4096) =
                make_uint4(pack_h2(f0.x, f0.y), pack_h2(f0.z, f0.w),
                           pack_h2(f1.x, f1.y), pack_h2(f1.z, f1.w));
        }
    };

    // prologue: convert q0 -> bh[0]; ensure q1 arrived; publish
    convert_quad(0);
    CP_WAIT(1);
    __syncthreads();

    // ================= main loop: 16 quads of 2 v =================
#pragma unroll 1
    for (int i = 0; i < NQUAD; i++) {
        if (i + 3 < NQUAD) { issue_quad(i + 3); CP_COMMIT(); CP_WAIT(1); }
        else CP_WAIT(0);

        // ---- MMA quad i (bh[i&1]) + weighted accumulate ----
        const float* wt = (const float*)(dsm + SM_WT + (i & 3) * 3072);
        uint32_t bhq = sb + SM_BH + (i & 1) * 8192;

#pragma unroll
        for (int vv = 0; vv < 2; vv++) {
            float acc[4][4];
#pragma unroll
            for (int nj = 0; nj < 4; nj++)
#pragma unroll
                for (int q = 0; q < 4; q++) acc[nj][q] = 0.0f;

            uint32_t bhbase = bhq + vv * 4096;
#pragma unroll
            for (int kk = 0; kk < 4; kk++) {
                int krow = kk * 16 + krl;
                uint32_t rowb = bhbase + krow * 64;
                uint32_t sw = (uint32_t)((krow >> 1) & 3);
                uint32_t bf0[4], bf1[4];
                LDSM4T(bf0, rowb + (((uint32_t)hi ^ sw) << 4));
                LDSM4T(bf1, rowb + (((uint32_t)(2 + hi) ^ sw) << 4));
                MMA16816(acc[0], af[kk], bf0[0], bf0[1]);
                MMA16816(acc[1], af[kk], bf0[2], bf0[3]);
                MMA16816(acc[2], af[kk], bf1[0], bf1[1]);
                MMA16816(acc[3], af[kk], bf1[2], bf1[3]);
            }

            int wb = vv * 384;
            if (lightW) {
                float w1 = wt[wb + b1], w2 = wt[wb + b2];
#pragma unroll
                for (int nj = 0; nj < 4; nj++) {
                    Tacc[nj * 4 + 0] += w1 * acc[nj][0];
                    Tacc[nj * 4 + 1] += w1 * acc[nj][1];
                    Tacc[nj * 4 + 2] += w2 * acc[nj][2];
                    Tacc[nj * 4 + 3] += w2 * acc[nj][3];
                }
            } else if (p == 3) {
                float w1 = v1a[0] * wt[wb + b1] + v1a[1] * wt[wb + 128 + b1]
                         + v1a[2] * wt[wb + 256 + b1];
                float w2 = v1b[0] * wt[wb + b2] + v1b[1] * wt[wb + 128 + b2]
                         + v1b[2] * wt[wb + 256 + b2];
#pragma unroll
                for (int nj = 0; nj < 4; nj++) {
                    Tacc[nj * 4 + 0] += w1 * acc[nj][0];
                    Tacc[nj * 4 + 1] += w1 * acc[nj][1];
                    Tacc[nj * 4 + 2] += w2 * acc[nj][2];
                    Tacc[nj * 4 + 3] += w2 * acc[nj][3];
                }
            } else {
                // p1 and p4: plain v2 weights, 3 sets (p4 cross in epilogue)
#pragma unroll
                for (int s = 0; s < 3; s++) {
                    float wa = wt[wb + s * 128 + b1];
                    float wb3 = wt[wb + s * 128 + b2];
#pragma unroll
                    for (int nj = 0; nj < 4; nj++) {
                        Tacc[s * 16 + nj * 4 + 0] += wa  * acc[nj][0];
                        Tacc[s * 16 + nj * 4 + 1] += wa  * acc[nj][1];
                        Tacc[s * 16 + nj * 4 + 2] += wb3 * acc[nj][2];
                        Tacc[s * 16 + nj * 4 + 3] += wb3 * acc[nj][3];
                    }
                }
            }
        }

        // ---- convert quad i+1 -> bh[(i+1)&1] (overlaps MMA drain) ----
        if (i + 1 < NQUAD) convert_quad(i + 1);
        __syncthreads();
    }

    // ---- epilogue: apply u-factor, atomicAdd into g_T ----
    int wb0 = wh * 32 + (lane & 3) * 2;

    auto at_rows = [&](int row1, int row2, int set, float f1, float f2) {
#pragma unroll
        for (int nj = 0; nj < 4; nj++) {
            int w = wb0 + nj * 8;
            atomicAdd(&g_T[row1 * 64 + w],     f1 * Tacc[set * 16 + nj * 4 + 0]);
            atomicAdd(&g_T[row1 * 64 + w + 1], f1 * Tacc[set * 16 + nj * 4 + 1]);
            atomicAdd(&g_T[row2 * 64 + w],     f2 * Tacc[set * 16 + nj * 4 + 2]);
            atomicAdd(&g_T[row2 * 64 + w + 1], f2 * Tacc[set * 16 + nj * 4 + 3]);
        }
    };

    if (p == 0) {
        float s1a = x1[b1 * 256 + u], s1b = x1[b2 * 256 + u];
        at_rows(b1, b2, 0, s1a, s1b);
    } else if (p == 1) {
        float s1a = x1[b1 * 256 + u], s1b = x1[b2 * 256 + u];
#pragma unroll
        for (int j = 0; j < 3; j++)
            at_rows(128 + 3 * b1 + j, 128 + 3 * b2 + j, j, s1a, s1b);
    } else if (p == 2) {
#pragma unroll
        for (int i = 0; i < 3; i++)
            at_rows(512 + 3 * b1 + i, 512 + 3 * b2 + i, 0, v1a[i], v1b[i]);
    } else if (p == 3) {
        at_rows(896 + b1, 896 + b2, 0, 1.0f, 1.0f);
    } else {
        // p4: cross(v1, T-sets)_k in the epilogue (linearity)
#pragma unroll
        for (int k = 0; k < 3; k++) {
            int k1 = (k + 1) % 3, k2 = (k + 2) % 3;
            int r1 = 1024 + 3 * b1 + k, r2 = 1024 + 3 * b2 + k;
#pragma unroll
            for (int nj = 0; nj < 4; nj++) {
                int w = wb0 + nj * 8;
                float o0 = v1a[k1] * Tacc[k2*16 + nj*4 + 0] - v1a[k2] * Tacc[k1*16 + nj*4 + 0];
                float o1 = v1a[k1] * Tacc[k2*16 + nj*4 + 1] - v1a[k2] * Tacc[k1*16 + nj*4 + 1];
                float o2 = v1b[k1] * Tacc[k2*16 + nj*4 + 2] - v1b[k2] * Tacc[k1*16 + nj*4 + 2];
                float o3 = v1b[k1] * Tacc[k2*16 + nj*4 + 3] - v1b[k2] * Tacc[k1*16 + nj*4 + 3];
                atomicAdd(&g_T[r1 * 64 + w],     o0);
                atomicAdd(&g_T[r1 * 64 + w + 1], o1);
                atomicAdd(&g_T[r2 * 64 + w],     o2);
                atomicAdd(&g_T[r2 * 64 + w + 1], o3);
            }
        }
    }
}

// ---------------------------------------------------------------------------
// Kernel 4: combine — assemble output from g_T (360 KB, L2-hot)
// ---------------------------------------------------------------------------
__global__ __launch_bounds__(448) void combine_kernel(float* __restrict__ out)
{
    int b = blockIdx.x;
    int t = threadIdx.x;
    const float C = 0.011048543456039806f;       // 1/(64*sqrt(2))
    const float INV_SQ3 = 0.5773502691896258f;

    if (t < 64) {
        int w = t;
        out[b * 448 + w] = C * (g_T[b * 64 + w] + INV_SQ3 * g_T[(896 + b) * 64 + w]);
    } else if (t < 256) {
        int i = t - 64;
        int w = i / 3, c = i % 3;
        out[b * 448 + 64 + w * 3 + c] =
            C * (g_T[(128 + b * 3 + c) * 64 + w] + g_T[(512 + b * 3 + c) * 64 + w]);
    } else {
        int i = t - 256;
        int w = i / 3, k = i % 3;
        out[b * 448 + 256 + w * 3 + k] = C * g_T[(1024 + b * 3 + k) * 64 + w];
    }
}

// ---------------------------------------------------------------------------
static double host_phi_c()
{
    const double dz = 16.0 / 4000.0;
    const double inv_sqrt2pi = 0.3989422804014327;
    double sum = 0.0, prev = 0.0;
    for (int i = 0; i <= 4000; i++) {
        double z = -8.0 + dz * (double)i;
        float xf = (float)z;
        float x3 = xf * xf * xf;
        float gg = 0.5f * xf * (1.0f + tanhf(0.7978845608028654f * (xf + 0.044715f * x3)));
        double f = (double)gg * (double)gg * exp(-0.5 * z * z) * inv_sqrt2pi;
        if (i > 0) sum += 0.5 * (f + prev) * dz;
        prev = f;
    }
    return sqrt(sum);
}

extern "C" void kernel_launch(void* const* d_in, const int* in_sizes, int n_in,
                              void* d_out, int out_size)
{
    const float* emb = (const float*)d_in[0];
    const float* x1  = (const float*)d_in[1];
    const float* x2  = (const float*)d_in[2];
    const float* W0  = (const float*)d_in[3];
    const float* W1  = (const float*)d_in[4];
    const float* W2  = (const float*)d_in[5];
    const float* P0  = (const float*)d_in[6];
    const float* P1  = (const float*)d_in[7];
    const float* P2  = (const float*)d_in[8];
    const float* P3  = (const float*)d_in[9];
    const float* P4  = (const float*)d_in[10];
    float* out = (float*)d_out;

    float phi_inv = (float)(1.0 / host_phi_c());

    cudaFuncSetAttribute(fused_kernel,
                         cudaFuncAttributeMaxDynamicSharedMemorySize, FUSED_DSMEM);

    mlp_kernel<<<128, 256>>>(emb, W0, W1, W2, phi_inv);
    prep_kernel<<<88, 1024>>>(x2);
    fused_kernel<<<dim3(64, 2, 10), 256, FUSED_DSMEM>>>(P0, P1, P2, P3, P4, x1);
    combine_kernel<<<128, 448>>>(out);
}